// round 4
// baseline (speedup 1.0000x reference)
#include <cuda_runtime.h>

// Problem constants (from reference)
#define BATCH   16384
#define NNEG    10
#define DD      8
#define EE      64
#define NSCORES (BATCH * (1 + NNEG))   // 180224

// One warp per score, 256-bit gathers with L2 evict-last.
//   quarter = lane>>3 (0..3): lane owns rows {quarter, quarter+4}
//   o       = lane&7  (0..7): lane owns columns [8o, 8o+8)   (32B = v4.b64)
// Each LDG.256 covers 4 complete 256B rows across the warp, fully coalesced.
// 2 loads/lane (was 8 in R1). evict_last keeps the ~121MB touched table set
// resident in the 126MB L2 across graph replays.
//
// pair_sum = sum_{i<j} e_i.e_j = 0.5*(||sum_r e_r||^2 - sum_r ||e_r||^2)
// Column sum S_j gathered over 4 lanes (xor 8, xor 16); per-lane contribution
// s_j*S_j sums to S_j^2 over the group, so 0.5*(sum_j s_j*S_j - sum v^2)
// butterfly-reduced over the warp gives the exact pair_sum.

__device__ __forceinline__ void ldg256_el(const float* p, float4& a, float4& b) {
    unsigned long long r0, r1, r2, r3;
    asm("ld.global.nc.L2::evict_last.v4.b64 {%0,%1,%2,%3}, [%4];"
        : "=l"(r0), "=l"(r1), "=l"(r2), "=l"(r3)
        : "l"(p));
    a.x = __uint_as_float((unsigned)r0);  a.y = __uint_as_float((unsigned)(r0 >> 32));
    a.z = __uint_as_float((unsigned)r1);  a.w = __uint_as_float((unsigned)(r1 >> 32));
    b.x = __uint_as_float((unsigned)r2);  b.y = __uint_as_float((unsigned)(r2 >> 32));
    b.z = __uint_as_float((unsigned)r3);  b.w = __uint_as_float((unsigned)(r3 >> 32));
}

__global__ __launch_bounds__(256) void APE_61555471286335_kernel(
    const int* __restrict__ pos_x,     // [BATCH, DD]
    const int* __restrict__ neg_x,     // [BATCH, NNEG, DD]
    const float* __restrict__ emb,     // [N_ENT, EE]
    const float* __restrict__ pair_w,  // [28]
    const float* __restrict__ c,       // [1]
    float* __restrict__ out)           // [NSCORES] = [pos(B) | neg(B*NNEG)]
{
    const int warp_global = (blockIdx.x * blockDim.x + threadIdx.x) >> 5;
    const int lane = threadIdx.x & 31;
    if (warp_global >= NSCORES) return;

    const int quarter = lane >> 3;     // row group
    const int o       = lane & 7;      // column group (8 cols each)

    // Fetch the 8 row indices (lanes 0..7 load, then broadcast).
    const int* idx_ptr = (warp_global < BATCH)
                       ? (pos_x + (size_t)warp_global * DD)
                       : (neg_x + (size_t)(warp_global - BATCH) * DD);
    int my_idx = 0;
    if (lane < DD) my_idx = __ldg(idx_ptr + lane);

    const int i0 = __shfl_sync(0xffffffffu, my_idx, quarter);
    const int i1 = __shfl_sync(0xffffffffu, my_idx, quarter + 4);

    // Two independent 256-bit gathers (issued back-to-back).
    float4 a0, a1, b0, b1;
    ldg256_el(emb + (size_t)i0 * EE + o * 8, a0, a1);
    ldg256_el(emb + (size_t)i1 * EE + o * 8, b0, b1);

    const float scale = expf(__ldg(pair_w));  // exp(pair_w[0]) — faithful to ref
    const float bias  = __ldg(c);

    // Per-column partials over this lane's 2 rows; sum of squares of all 16 vals.
    float s[8];
    s[0] = a0.x + b0.x;  s[1] = a0.y + b0.y;
    s[2] = a0.z + b0.z;  s[3] = a0.w + b0.w;
    s[4] = a1.x + b1.x;  s[5] = a1.y + b1.y;
    s[6] = a1.z + b1.z;  s[7] = a1.w + b1.w;

    float sq = 0.f;
    sq = fmaf(a0.x, a0.x, sq); sq = fmaf(a0.y, a0.y, sq);
    sq = fmaf(a0.z, a0.z, sq); sq = fmaf(a0.w, a0.w, sq);
    sq = fmaf(a1.x, a1.x, sq); sq = fmaf(a1.y, a1.y, sq);
    sq = fmaf(a1.z, a1.z, sq); sq = fmaf(a1.w, a1.w, sq);
    sq = fmaf(b0.x, b0.x, sq); sq = fmaf(b0.y, b0.y, sq);
    sq = fmaf(b0.z, b0.z, sq); sq = fmaf(b0.w, b0.w, sq);
    sq = fmaf(b1.x, b1.x, sq); sq = fmaf(b1.y, b1.y, sq);
    sq = fmaf(b1.z, b1.z, sq); sq = fmaf(b1.w, b1.w, sq);

    // Full column sums across the 4 lanes sharing this column group.
    float t = 0.f;
#pragma unroll
    for (int j = 0; j < 8; j++) {
        float w = s[j] + __shfl_xor_sync(0xffffffffu, s[j], 8);
        float S = w + __shfl_xor_sync(0xffffffffu, w, 16);
        t = fmaf(s[j], S, t);   // sums to S^2 over the 4-lane group
    }

    float partial = 0.5f * (t - sq);

    // Butterfly reduction over 32 lanes.
#pragma unroll
    for (int off = 16; off; off >>= 1)
        partial += __shfl_xor_sync(0xffffffffu, partial, off);

    if (lane == 0)
        out[warp_global] = expf(fmaf(partial, scale, bias));
}

extern "C" void kernel_launch(void* const* d_in, const int* in_sizes, int n_in,
                              void* d_out, int out_size) {
    const int*   pos_x  = (const int*)d_in[0];
    const int*   neg_x  = (const int*)d_in[1];
    const float* emb    = (const float*)d_in[2];
    const float* pair_w = (const float*)d_in[3];
    const float* c      = (const float*)d_in[4];
    float*       out    = (float*)d_out;

    const int threads = 256;                       // 8 warps = 8 scores / block
    const int blocks = (NSCORES * 32 + threads - 1) / threads;  // 22528
    APE_61555471286335_kernel<<<blocks, threads>>>(pos_x, neg_x, emb, pair_w, c, out);
}

// round 5
// speedup vs baseline: 1.4275x; 1.4275x over previous
#include <cuda_runtime.h>

// Problem constants (from reference)
#define BATCH   16384
#define NNEG    10
#define DD      8
#define EE      64
#define NSCORES (BATCH * (1 + NNEG))   // 180224
#define NWARPS  (NSCORES / 2)          // 90112 (two scores per warp)

// Two scores per warp, one per half-warp.
//   h  = lane>>4 : which score this lane works on (score = 2*warp + h)
//   hl = lane&15 : column group; lane owns cols [4*hl, 4*hl+4) (float4)
// Each row load: 16 lanes x 16B = one 256B row, fully coalesced.
// 8 independent float4 gathers per lane -> 4KB in flight per warp (2x R1)
// to close the latency gap toward the LTS throughput cap.
//
// pair_sum = sum_{i<j} e_i.e_j = 0.5*(||sum_r e_r||^2 - sum_r ||e_r||^2)
// Column sums complete within a lane (it sees all 8 rows), so
// partial = 0.5*(sum_j S_j^2 - sum v^2), reduced over the 16-lane half.

__global__ __launch_bounds__(256) void APE_61555471286335_kernel(
    const int* __restrict__ pos_x,     // [BATCH, DD]
    const int* __restrict__ neg_x,     // [BATCH, NNEG, DD]
    const float* __restrict__ emb,     // [N_ENT, EE]
    const float* __restrict__ pair_w,  // [28]
    const float* __restrict__ c,       // [1]
    float* __restrict__ out)           // [NSCORES] = [pos(B) | neg(B*NNEG)]
{
    const int warp_global = (blockIdx.x * blockDim.x + threadIdx.x) >> 5;
    const int lane = threadIdx.x & 31;
    if (warp_global >= NWARPS) return;

    const int h  = lane >> 4;              // which score in this warp
    const int hl = lane & 15;              // column group within the half
    const int score = 2 * warp_global + h;

    // Fetch this half's 8 row indices (lanes hl<8 load, then broadcast).
    const int* idx_ptr = (score < BATCH)
                       ? (pos_x + (size_t)score * DD)
                       : (neg_x + (size_t)(score - BATCH) * DD);
    int my_idx = 0;
    if (hl < DD) my_idx = __ldg(idx_ptr + hl);

    int rows[DD];
#pragma unroll
    for (int r = 0; r < DD; r++)
        rows[r] = __shfl_sync(0xffffffffu, my_idx, (h << 4) + r);

    // Issue all 8 gathers back-to-back (MLP=8 per lane, 16 rows per warp).
    float4 v[DD];
#pragma unroll
    for (int r = 0; r < DD; r++)
        v[r] = __ldg(reinterpret_cast<const float4*>(
                         emb + (size_t)rows[r] * EE) + hl);

    const float scale = expf(__ldg(pair_w));  // exp(pair_w[0]) — faithful to ref
    const float bias  = __ldg(c);

    // Column sums over the 8 rows + sum of squares.
    float s0 = 0.f, s1 = 0.f, s2 = 0.f, s3 = 0.f, sq = 0.f;
#pragma unroll
    for (int r = 0; r < DD; r++) {
        s0 += v[r].x;  s1 += v[r].y;  s2 += v[r].z;  s3 += v[r].w;
        sq = fmaf(v[r].x, v[r].x, sq);
        sq = fmaf(v[r].y, v[r].y, sq);
        sq = fmaf(v[r].z, v[r].z, sq);
        sq = fmaf(v[r].w, v[r].w, sq);
    }

    float t = s0 * s0 + s1 * s1 + s2 * s2 + s3 * s3;
    float partial = 0.5f * (t - sq);

    // Reduce over the 16 lanes of this half (xor offsets stay in-half).
#pragma unroll
    for (int off = 8; off; off >>= 1)
        partial += __shfl_xor_sync(0xffffffffu, partial, off);

    if (hl == 0)
        out[score] = expf(fmaf(partial, scale, bias));
}

extern "C" void kernel_launch(void* const* d_in, const int* in_sizes, int n_in,
                              void* d_out, int out_size) {
    const int*   pos_x  = (const int*)d_in[0];
    const int*   neg_x  = (const int*)d_in[1];
    const float* emb    = (const float*)d_in[2];
    const float* pair_w = (const float*)d_in[3];
    const float* c      = (const float*)d_in[4];
    float*       out    = (float*)d_out;

    const int threads = 256;                            // 8 warps = 16 scores / block
    const int blocks = (NWARPS * 32 + threads - 1) / threads;  // 11264
    APE_61555471286335_kernel<<<blocks, threads>>>(pos_x, neg_x, emb, pair_w, c, out);
}

// round 6
// speedup vs baseline: 1.4398x; 1.0087x over previous
#include <cuda_runtime.h>

// Problem constants (from reference)
#define BATCH   16384
#define NNEG    10
#define DD      8
#define EE      64
#define NSCORES (BATCH * (1 + NNEG))   // 180224
#define NWARPS  (NSCORES / 4)          // 45056 (four scores per warp)

// Four scores per warp, one per 8-lane quarter.
//   q = lane>>3 : score slot (score = 4*warp + q)
//   o = lane&7  : column octet; lane owns cols [8o, 8o+8)  (32B, one LDG.256)
// Each row: 8 lanes x 32B = one 256B row, fully coalesced per quarter.
// 8 independent 256-bit gathers per lane -> 8KB in flight per warp (2x R5),
// pushing the latency-exposed random-gather stream toward the DRAM roofline.
//
// pair_sum = sum_{i<j} e_i.e_j = 0.5*(||sum_r e_r||^2 - sum_r ||e_r||^2)
// Column sums complete within a lane (it sees all 8 rows of its 8 columns):
// partial = 0.5*(sum_j S_j^2 - sum v^2), reduced over the 8-lane quarter.

__device__ __forceinline__ void ldg256(const float* p, float4& a, float4& b) {
    unsigned long long r0, r1, r2, r3;
    asm("ld.global.nc.v4.b64 {%0,%1,%2,%3}, [%4];"
        : "=l"(r0), "=l"(r1), "=l"(r2), "=l"(r3)
        : "l"(p));
    a.x = __uint_as_float((unsigned)r0);  a.y = __uint_as_float((unsigned)(r0 >> 32));
    a.z = __uint_as_float((unsigned)r1);  a.w = __uint_as_float((unsigned)(r1 >> 32));
    b.x = __uint_as_float((unsigned)r2);  b.y = __uint_as_float((unsigned)(r2 >> 32));
    b.z = __uint_as_float((unsigned)r3);  b.w = __uint_as_float((unsigned)(r3 >> 32));
}

__global__ __launch_bounds__(256) void APE_61555471286335_kernel(
    const int* __restrict__ pos_x,     // [BATCH, DD]
    const int* __restrict__ neg_x,     // [BATCH, NNEG, DD]
    const float* __restrict__ emb,     // [N_ENT, EE]
    const float* __restrict__ pair_w,  // [28]
    const float* __restrict__ c,       // [1]
    float* __restrict__ out)           // [NSCORES] = [pos(B) | neg(B*NNEG)]
{
    const int warp_global = (blockIdx.x * blockDim.x + threadIdx.x) >> 5;
    const int lane = threadIdx.x & 31;
    if (warp_global >= NWARPS) return;

    const int q = lane >> 3;               // score slot in this warp
    const int o = lane & 7;                // column octet
    const int score = 4 * warp_global + q;

    // 32 indices per warp == 32 lanes: lane loads idx[slot q][element o].
    const int* idx_ptr = (score < BATCH)
                       ? (pos_x + (size_t)score * DD)
                       : (neg_x + (size_t)(score - BATCH) * DD);
    const int my_idx = __ldg(idx_ptr + o);

    int rows[DD];
#pragma unroll
    for (int r = 0; r < DD; r++)
        rows[r] = __shfl_sync(0xffffffffu, my_idx, (q << 3) + r);

    // Issue all 8 independent 256-bit gathers back-to-back.
    float4 va[DD], vb[DD];
#pragma unroll
    for (int r = 0; r < DD; r++)
        ldg256(emb + (size_t)rows[r] * EE + o * 8, va[r], vb[r]);

    const float scale = expf(__ldg(pair_w));  // exp(pair_w[0]) — faithful to ref
    const float bias  = __ldg(c);

    // Column sums over the 8 rows + sum of squares (8 columns per lane).
    float s0=0.f,s1=0.f,s2=0.f,s3=0.f,s4=0.f,s5=0.f,s6=0.f,s7=0.f,sq=0.f;
#pragma unroll
    for (int r = 0; r < DD; r++) {
        s0 += va[r].x;  s1 += va[r].y;  s2 += va[r].z;  s3 += va[r].w;
        s4 += vb[r].x;  s5 += vb[r].y;  s6 += vb[r].z;  s7 += vb[r].w;
        sq = fmaf(va[r].x, va[r].x, sq);
        sq = fmaf(va[r].y, va[r].y, sq);
        sq = fmaf(va[r].z, va[r].z, sq);
        sq = fmaf(va[r].w, va[r].w, sq);
        sq = fmaf(vb[r].x, vb[r].x, sq);
        sq = fmaf(vb[r].y, vb[r].y, sq);
        sq = fmaf(vb[r].z, vb[r].z, sq);
        sq = fmaf(vb[r].w, vb[r].w, sq);
    }

    float t = s0*s0 + s1*s1 + s2*s2 + s3*s3
            + s4*s4 + s5*s5 + s6*s6 + s7*s7;
    float partial = 0.5f * (t - sq);

    // Reduce over the 8 lanes of this quarter (xor 1,2,4 stay in-quarter).
#pragma unroll
    for (int off = 4; off; off >>= 1)
        partial += __shfl_xor_sync(0xffffffffu, partial, off);

    if (o == 0)
        out[score] = expf(fmaf(partial, scale, bias));
}

extern "C" void kernel_launch(void* const* d_in, const int* in_sizes, int n_in,
                              void* d_out, int out_size) {
    const int*   pos_x  = (const int*)d_in[0];
    const int*   neg_x  = (const int*)d_in[1];
    const float* emb    = (const float*)d_in[2];
    const float* pair_w = (const float*)d_in[3];
    const float* c      = (const float*)d_in[4];
    float*       out    = (float*)d_out;

    const int threads = 256;                            // 8 warps = 32 scores / block
    const int blocks = (NWARPS * 32 + threads - 1) / threads;  // 5632
    APE_61555471286335_kernel<<<blocks, threads>>>(pos_x, neg_x, emb, pair_w, c, out);
}